// round 1
// baseline (speedup 1.0000x reference)
#include <cuda_runtime.h>
#include <math.h>

#define N_INP 128
#define N_HID 512
#define N_OUT 256
#define N_HEADS 64
#define N_SM 4
#define EPS_GN 1e-5f
#define TINY 1e-14f

// Scratch (no allocations allowed): device globals.
__device__ float g_h1[N_HEADS * N_HID];                 // softplus(GN(w1@sub))
__device__ float g_p[N_SM * N_OUT * N_HEADS];           // per-s softmax probs, [s][o][h]
__device__ float g_outsm[N_OUT * N_HEADS];              // sum over s, [o][h]
__device__ float g_scalar[N_OUT * N_HEADS];             // ws.sum(-1).T, [o][h]
__device__ float g_onoff[N_HEADS];

__device__ __forceinline__ float wsum(float v) {
#pragma unroll
    for (int o = 16; o > 0; o >>= 1) v += __shfl_xor_sync(0xffffffffu, v, o);
    return v;
}
__device__ __forceinline__ float wmax(float v) {
#pragma unroll
    for (int o = 16; o > 0; o >>= 1) v = fmaxf(v, __shfl_xor_sync(0xffffffffu, v, o));
    return v;
}

// ---------------- Kernel A: sub = x @ qw_h ; h1 = softplus(GN(w1_h @ sub)) ----------------
__global__ __launch_bounds__(256) void kA(const float* __restrict__ x,
                                          const float* __restrict__ qw,
                                          const float* __restrict__ w1,
                                          const float* __restrict__ g1,
                                          const float* __restrict__ b1) {
    int h = blockIdx.x, t = threadIdx.x, w = t >> 5, l = t & 31;
    __shared__ float qs[128], sub[128], z1[512];
    __shared__ float rs[8], rss[8], stat[2];

    if (t < 128) qs[t] = qw[h * 128 + t];
    __syncthreads();

    // sub[r] = dot(x[r,:], qw[h,:]) — warp per row, float4 coalesced
    for (int r = w; r < 128; r += 8) {
        float4 a = *(const float4*)(x + r * 128 + l * 4);
        int i = l * 4;
        float d = a.x * qs[i] + a.y * qs[i + 1] + a.z * qs[i + 2] + a.w * qs[i + 3];
        d = wsum(d);
        if (l == 0) sub[r] = d;
    }
    __syncthreads();

    // z1[o] = dot(w1[h,o,:], sub)
    const float* w1h = w1 + (size_t)h * 512 * 128;
    for (int o = w; o < 512; o += 8) {
        float4 a = *(const float4*)(w1h + o * 128 + l * 4);
        int i = l * 4;
        float d = a.x * sub[i] + a.y * sub[i + 1] + a.z * sub[i + 2] + a.w * sub[i + 3];
        d = wsum(d);
        if (l == 0) z1[o] = d;
    }
    __syncthreads();

    // GroupNorm stats over 512 (biased variance)
    float s = 0.f, ss = 0.f;
    for (int o = t; o < 512; o += 256) { float v = z1[o]; s += v; ss += v * v; }
    s = wsum(s); ss = wsum(ss);
    if (l == 0) { rs[w] = s; rss[w] = ss; }
    __syncthreads();
    if (t == 0) {
        float S = 0.f, SS = 0.f;
#pragma unroll
        for (int i = 0; i < 8; i++) { S += rs[i]; SS += rss[i]; }
        float mu = S / 512.f;
        float var = SS / 512.f - mu * mu;
        stat[0] = mu;
        stat[1] = rsqrtf(fmaxf(var, 0.f) + EPS_GN);
    }
    __syncthreads();
    float mu = stat[0], ri = stat[1];
    for (int o = t; o < 512; o += 256) {
        float v = (z1[o] - mu) * ri * g1[h * 512 + o] + b1[h * 512 + o];
        // softplus = max(v,0) + log1p(exp(-|v|))
        g_h1[h * 512 + o] = fmaxf(v, 0.f) + log1pf(expf(-fabsf(v)));
    }
}

// ---------------- Kernel B: z = GN(w2[s,h] @ h1) ; softmax over n_out -> g_p ----------------
__global__ __launch_bounds__(512) void kB(const float* __restrict__ w2,
                                          const float* __restrict__ g2,
                                          const float* __restrict__ b2) {
    int h = blockIdx.x, s = blockIdx.y, t = threadIdx.x, w = t >> 5, l = t & 31;
    __shared__ float h1s[512], zs[256];
    __shared__ float r1[16], r2[16], stat[2];

    h1s[t] = g_h1[h * 512 + t];
    __syncthreads();

    // 256 rows of 512-dot; warp per row, 4x float4 per lane (fully coalesced)
    const float* base = w2 + ((size_t)(s * 64 + h)) * 256 * 512;
    for (int o = w; o < 256; o += 16) {
        const float* row = base + (size_t)o * 512;
        float d = 0.f;
#pragma unroll
        for (int k = 0; k < 4; k++) {
            float4 a = *(const float4*)(row + k * 128 + l * 4);
            int i = k * 128 + l * 4;
            d += a.x * h1s[i] + a.y * h1s[i + 1] + a.z * h1s[i + 2] + a.w * h1s[i + 3];
        }
        d = wsum(d);
        if (l == 0) zs[o] = d;
    }
    __syncthreads();

    // GN stats over 256
    float v = (t < 256) ? zs[t] : 0.f;
    float sv = wsum(v), sq = wsum(v * v);
    if (l == 0) { r1[w] = sv; r2[w] = sq; }
    __syncthreads();
    if (t == 0) {
        float S = 0.f, SS = 0.f;
#pragma unroll
        for (int i = 0; i < 16; i++) { S += r1[i]; SS += r2[i]; }
        float mu = S / 256.f;
        float var = SS / 256.f - mu * mu;
        stat[0] = mu;
        stat[1] = rsqrtf(fmaxf(var, 0.f) + EPS_GN);
    }
    __syncthreads();
    float mu = stat[0], ri = stat[1];
    size_t gidx = ((size_t)(s * 64 + h)) * 256;
    if (t < 256) zs[t] = (zs[t] - mu) * ri * g2[gidx + t] + b2[gidx + t];
    __syncthreads();

    // stable softmax over 256
    float m = (t < 256) ? zs[t] : -1e30f;
    m = wmax(m);
    if (l == 0) r1[w] = m;
    __syncthreads();
    if (t == 0) {
        float M = -1e30f;
#pragma unroll
        for (int i = 0; i < 16; i++) M = fmaxf(M, r1[i]);
        stat[0] = M;
    }
    __syncthreads();
    float M = stat[0];
    float e = (t < 256) ? expf(zs[t] - M) : 0.f;
    float se = wsum(e);
    if (l == 0) r2[w] = se;
    __syncthreads();
    if (t == 0) {
        float S = 0.f;
#pragma unroll
        for (int i = 0; i < 16; i++) S += r2[i];
        stat[1] = S;
    }
    __syncthreads();
    if (t < 256) g_p[((size_t)s * 256 + t) * 64 + h] = e / stat[1];
}

// ---------------- Kernel C: scalar[o,h] = sum_j ws[h,o,j] ----------------
__global__ __launch_bounds__(256) void kC(const float* __restrict__ ws) {
    int h = blockIdx.x, t = threadIdx.x, w = t >> 5, l = t & 31;
    const float* wsh = ws + (size_t)h * 256 * 256;
    for (int o = w; o < 256; o += 8) {
        float s = 0.f;
#pragma unroll
        for (int k = 0; k < 2; k++) {
            float4 a = *(const float4*)(wsh + o * 256 + k * 128 + l * 4);
            s += a.x + a.y + a.z + a.w;
        }
        s = wsum(s);
        if (l == 0) g_scalar[o * 64 + h] = s;
    }
}

// ---------------- Kernel D0: out_sm = sum_s g_p ----------------
__global__ __launch_bounds__(256) void kD0() {
    int i = blockIdx.x * 256 + threadIdx.x;
    if (i < 16384) {
        g_outsm[i] = g_p[i] + g_p[16384 + i] + g_p[2 * 16384 + i] + g_p[3 * 16384 + i];
    }
}

// ---------------- Kernel D1: gate logits + sigmoid ----------------
__global__ __launch_bounds__(256) void kD1(const float* __restrict__ last,
                                           const float* __restrict__ woo) {
    __shared__ float lp[256];
    int t = threadIdx.x, w = t >> 5, l = t & 31;
    float p = 1.f;
    const float* lo = last + t * 64;
#pragma unroll 8
    for (int i = 0; i < 64; i++) p *= lo[i];
    lp[t] = p;
    __syncthreads();
    for (int h = w; h < 64; h += 8) {
        const float* wh = woo + h * 512;
        float d = 0.f;
        for (int o = l; o < 256; o += 32)
            d += wh[o] * lp[o] + wh[256 + o] * g_outsm[o * 64 + h];
        d = wsum(d);
        if (l == 0) g_onoff[h] = 1.f / (1.f + expf(-d));
    }
}

// ---------------- Kernel D2: final elementwise outputs ----------------
__global__ __launch_bounds__(256) void kD2(float* __restrict__ out) {
    int i = blockIdx.x * 256 + threadIdx.x;
    if (i < 16384) {
        float v = g_onoff[i & 63] * g_outsm[i];
        out[i] = fmaxf(v, TINY);                       // clip(on_off_out_sm, TINY, None)
        float sc = v * g_scalar[i];
        out[16384 + i] = (fabsf(sc) <= TINY) ? TINY : sc;
    }
}

extern "C" void kernel_launch(void* const* d_in, const int* in_sizes, int n_in,
                              void* d_out, int out_size) {
    const float* x    = (const float*)d_in[0];
    const float* last = (const float*)d_in[1];
    const float* qw   = (const float*)d_in[2];
    const float* w1   = (const float*)d_in[3];
    const float* g1   = (const float*)d_in[4];
    const float* b1   = (const float*)d_in[5];
    const float* w2   = (const float*)d_in[6];
    const float* g2   = (const float*)d_in[7];
    const float* b2   = (const float*)d_in[8];
    const float* ws   = (const float*)d_in[9];
    const float* woo  = (const float*)d_in[10];
    float* out = (float*)d_out;

    kA<<<64, 256>>>(x, qw, w1, g1, b1);
    kB<<<dim3(64, 4), 512>>>(w2, g2, b2);
    kC<<<64, 256>>>(ws);
    kD0<<<64, 256>>>();
    kD1<<<1, 256>>>(last, woo);
    kD2<<<64, 256>>>(out);
}

// round 2
// speedup vs baseline: 1.6817x; 1.6817x over previous
#include <cuda_runtime.h>
#include <math.h>

#define N_INP 128
#define N_HID 512
#define N_OUT 256
#define N_HEADS 64
#define N_SM 4
#define EPS_GN 1e-5f
#define TINY 1e-14f

// Scratch: device globals (no allocation allowed).
__device__ float g_sub[N_HEADS * N_INP];        // [h][r]
__device__ float g_z1[N_HEADS * N_HID];         // pre-GN l1 activations
__device__ float g_h1[N_HEADS * N_HID];         // softplus(GN(z1))
__device__ float g_z[N_SM * N_HEADS * N_OUT];   // pre-GN l2 activations [s][h][o]
__device__ float g_outsm[N_OUT * N_HEADS];      // sum_s softmax, [o][h]
__device__ float g_scalar[N_OUT * N_HEADS];     // ws.sum(-1).T, [o][h]
__device__ float g_gate2[N_HEADS];              // sum_o woo[h,256+o]*outsm[o,h]
__device__ float g_onoff[N_HEADS];

__device__ __forceinline__ float wsum(float v) {
#pragma unroll
    for (int o = 16; o > 0; o >>= 1) v += __shfl_xor_sync(0xffffffffu, v, o);
    return v;
}
__device__ __forceinline__ float wmax(float v) {
#pragma unroll
    for (int o = 16; o > 0; o >>= 1) v = fmaxf(v, __shfl_xor_sync(0xffffffffu, v, o));
    return v;
}

// ---------------- k0: sub[h][r] = dot(x[r,:], qw[h,:]) ----------------
__global__ __launch_bounds__(256) void k0(const float* __restrict__ x,
                                          const float* __restrict__ qw) {
    int h = blockIdx.x, t = threadIdx.x, w = t >> 5, l = t & 31;
    __shared__ float qs[128];
    if (t < 128) qs[t] = qw[h * 128 + t];
    __syncthreads();
    float s0 = qs[l * 4], s1 = qs[l * 4 + 1], s2 = qs[l * 4 + 2], s3 = qs[l * 4 + 3];
    // 8 warps, 16 rows each, 8-row ILP
#pragma unroll
    for (int g = 0; g < 2; ++g) {
        int r = w * 16 + g * 8;
        float acc[8];
        float4 a[8];
#pragma unroll
        for (int j = 0; j < 8; ++j)
            a[j] = *(const float4*)(x + (r + j) * 128 + l * 4);
#pragma unroll
        for (int j = 0; j < 8; ++j)
            acc[j] = a[j].x * s0 + a[j].y * s1 + a[j].z * s2 + a[j].w * s3;
#pragma unroll
        for (int j = 0; j < 8; ++j) acc[j] = wsum(acc[j]);
        if (l == 0) {
#pragma unroll
            for (int j = 0; j < 8; ++j) g_sub[h * 128 + r + j] = acc[j];
        }
    }
}

// ---------------- k1: z1[h][o] = dot(w1[h,o,:], sub[h]) ; 256 blocks ----------------
__global__ __launch_bounds__(256) void k1(const float* __restrict__ w1) {
    int h = blockIdx.x >> 2, c = blockIdx.x & 3;
    int t = threadIdx.x, w = t >> 5, l = t & 31;
    __shared__ float sub[128];
    if (t < 128) sub[t] = g_sub[h * 128 + t];
    __syncthreads();
    float s0 = sub[l * 4], s1 = sub[l * 4 + 1], s2 = sub[l * 4 + 2], s3 = sub[l * 4 + 3];
    const float* w1b = w1 + (size_t)h * 512 * 128 + (size_t)c * 128 * 128;
    // 128 rows per block, 8 warps -> 16 rows/warp, 8-row ILP
#pragma unroll
    for (int g = 0; g < 2; ++g) {
        int r = w * 16 + g * 8;
        float4 a[8];
        float acc[8];
#pragma unroll
        for (int j = 0; j < 8; ++j)
            a[j] = *(const float4*)(w1b + (r + j) * 128 + l * 4);
#pragma unroll
        for (int j = 0; j < 8; ++j)
            acc[j] = a[j].x * s0 + a[j].y * s1 + a[j].z * s2 + a[j].w * s3;
#pragma unroll
        for (int j = 0; j < 8; ++j) acc[j] = wsum(acc[j]);
        if (l == 0) {
#pragma unroll
            for (int j = 0; j < 8; ++j) g_z1[h * 512 + c * 128 + r + j] = acc[j];
        }
    }
}

// ---------------- k2: h1 = softplus(GN(z1)) per head ----------------
__global__ __launch_bounds__(256) void k2(const float* __restrict__ g1,
                                          const float* __restrict__ b1) {
    int h = blockIdx.x, t = threadIdx.x, w = t >> 5, l = t & 31;
    __shared__ float rs[8], rss[8], stat[2];
    float v0 = g_z1[h * 512 + t], v1 = g_z1[h * 512 + 256 + t];
    float s = v0 + v1, ss = v0 * v0 + v1 * v1;
    s = wsum(s); ss = wsum(ss);
    if (l == 0) { rs[w] = s; rss[w] = ss; }
    __syncthreads();
    if (t == 0) {
        float S = 0.f, SS = 0.f;
#pragma unroll
        for (int i = 0; i < 8; ++i) { S += rs[i]; SS += rss[i]; }
        float mu = S / 512.f;
        float var = SS / 512.f - mu * mu;
        stat[0] = mu;
        stat[1] = rsqrtf(fmaxf(var, 0.f) + EPS_GN);
    }
    __syncthreads();
    float mu = stat[0], ri = stat[1];
    float a0 = (v0 - mu) * ri * g1[h * 512 + t] + b1[h * 512 + t];
    float a1 = (v1 - mu) * ri * g1[h * 512 + 256 + t] + b1[h * 512 + 256 + t];
    g_h1[h * 512 + t] = fmaxf(a0, 0.f) + log1pf(expf(-fabsf(a0)));
    g_h1[h * 512 + 256 + t] = fmaxf(a1, 0.f) + log1pf(expf(-fabsf(a1)));
}

// ---------------- k3: fused streamer: z matvec (1024 blocks) + ws sums (128 blocks) ----------------
__global__ __launch_bounds__(256) void k3(const float* __restrict__ w2,
                                          const float* __restrict__ ws) {
    int b = blockIdx.x;
    int t = threadIdx.x, w = t >> 5, l = t & 31;
    if (b < 1024) {
        // z[s][h][chunk of 64 rows]
        int c = b & 3, h = (b >> 2) & 63, s = b >> 8;
        __shared__ float h1s[512];
        h1s[t] = g_h1[h * 512 + t];
        h1s[t + 256] = g_h1[h * 512 + 256 + t];
        __syncthreads();
        const float* base = w2 + ((size_t)(s * 64 + h)) * 256 * 512 + (size_t)c * 64 * 512;
        // 64 rows, 8 warps -> 8 rows/warp; 2-row x 4-kchunk ILP = 8 LDG.128 in flight
#pragma unroll
        for (int g = 0; g < 4; ++g) {
            int r = w * 8 + g * 2;
            const float* r0 = base + (size_t)r * 512;
            const float* r1 = r0 + 512;
            float4 a[4], bq[4];
#pragma unroll
            for (int k = 0; k < 4; ++k) {
                a[k]  = *(const float4*)(r0 + k * 128 + l * 4);
                bq[k] = *(const float4*)(r1 + k * 128 + l * 4);
            }
            float d0 = 0.f, d1 = 0.f;
#pragma unroll
            for (int k = 0; k < 4; ++k) {
                int i = k * 128 + l * 4;
                d0 += a[k].x * h1s[i] + a[k].y * h1s[i + 1] + a[k].z * h1s[i + 2] + a[k].w * h1s[i + 3];
                d1 += bq[k].x * h1s[i] + bq[k].y * h1s[i + 1] + bq[k].z * h1s[i + 2] + bq[k].w * h1s[i + 3];
            }
            d0 = wsum(d0); d1 = wsum(d1);
            if (l == 0) {
                size_t o = (size_t)(s * 64 + h) * 256 + c * 64 + r;
                g_z[o] = d0;
                g_z[o + 1] = d1;
            }
        }
    } else {
        // ws row-sums: scalar[o][h] = sum_j ws[h][o][j]
        int idx = b - 1024;
        int h = idx >> 1, half = idx & 1;
        const float* base = ws + (size_t)h * 256 * 256 + (size_t)half * 128 * 256;
        // 128 rows, 8 warps -> 16 rows/warp; 4-row x 2-kchunk ILP
#pragma unroll
        for (int g = 0; g < 4; ++g) {
            int r = w * 16 + g * 4;
            float acc[4] = {0.f, 0.f, 0.f, 0.f};
            float4 a[8];
#pragma unroll
            for (int j = 0; j < 4; ++j) {
#pragma unroll
                for (int k = 0; k < 2; ++k)
                    a[j * 2 + k] = *(const float4*)(base + (size_t)(r + j) * 256 + k * 128 + l * 4);
            }
#pragma unroll
            for (int j = 0; j < 4; ++j) {
#pragma unroll
                for (int k = 0; k < 2; ++k)
                    acc[j] += a[j * 2 + k].x + a[j * 2 + k].y + a[j * 2 + k].z + a[j * 2 + k].w;
            }
#pragma unroll
            for (int j = 0; j < 4; ++j) acc[j] = wsum(acc[j]);
            if (l == 0) {
                int o = half * 128 + r;
#pragma unroll
                for (int j = 0; j < 4; ++j) g_scalar[(o + j) * 64 + h] = acc[j];
            }
        }
    }
}

// ---------------- k4: per-head GN+softmax over each s, sum over s, + gate partial ----------------
__global__ __launch_bounds__(256) void k4(const float* __restrict__ g2,
                                          const float* __restrict__ b2,
                                          const float* __restrict__ woo) {
    int h = blockIdx.x, t = threadIdx.x, w = t >> 5, l = t & 31;
    __shared__ float r1[8], r2[8], stat[2];
    float acc = 0.f;
#pragma unroll
    for (int s = 0; s < 4; ++s) {
        size_t gi = (size_t)(s * 64 + h) * 256;
        float v = g_z[gi + t];
        // GN stats (256 elems, 8 warps)
        float sv = wsum(v), sq = wsum(v * v);
        if (l == 0) { r1[w] = sv; r2[w] = sq; }
        __syncthreads();
        if (t == 0) {
            float S = 0.f, SS = 0.f;
#pragma unroll
            for (int i = 0; i < 8; ++i) { S += r1[i]; SS += r2[i]; }
            float mu = S / 256.f;
            float var = SS / 256.f - mu * mu;
            stat[0] = mu;
            stat[1] = rsqrtf(fmaxf(var, 0.f) + EPS_GN);
        }
        __syncthreads();
        float z = (v - stat[0]) * stat[1] * g2[gi + t] + b2[gi + t];
        __syncthreads();
        // softmax
        float m = wmax(z);
        if (l == 0) r1[w] = m;
        __syncthreads();
        if (t == 0) {
            float M = -1e30f;
#pragma unroll
            for (int i = 0; i < 8; ++i) M = fmaxf(M, r1[i]);
            stat[0] = M;
        }
        __syncthreads();
        float e = expf(z - stat[0]);
        float se = wsum(e);
        if (l == 0) r2[w] = se;
        __syncthreads();
        if (t == 0) {
            float S = 0.f;
#pragma unroll
            for (int i = 0; i < 8; ++i) S += r2[i];
            stat[1] = S;
        }
        __syncthreads();
        acc += e / stat[1];
        __syncthreads();
    }
    g_outsm[t * 64 + h] = acc;
    // gate partial: sum_o woo[h,256+o]*outsm[o,h]
    float gp = woo[h * 512 + 256 + t] * acc;
    gp = wsum(gp);
    if (l == 0) r1[w] = gp;
    __syncthreads();
    if (t == 0) {
        float S = 0.f;
#pragma unroll
        for (int i = 0; i < 8; ++i) S += r1[i];
        g_gate2[h] = S;
    }
}

// ---------------- k5: gate logits + sigmoid ----------------
__global__ __launch_bounds__(256) void k5(const float* __restrict__ last,
                                          const float* __restrict__ woo) {
    __shared__ float lp[256];
    int t = threadIdx.x, w = t >> 5, l = t & 31;
    float p = 1.f;
    const float* lo = last + t * 64;
#pragma unroll 8
    for (int i = 0; i < 64; ++i) p *= lo[i];
    lp[t] = p;
    __syncthreads();
    for (int h = w; h < 64; h += 8) {
        const float* wh = woo + h * 512;
        float d = 0.f;
#pragma unroll
        for (int o = 0; o < 8; ++o) d += wh[o * 32 + l] * lp[o * 32 + l];
        d = wsum(d);
        if (l == 0) g_onoff[h] = 1.f / (1.f + expf(-(d + g_gate2[h])));
    }
}

// ---------------- k6: final elementwise outputs ----------------
__global__ __launch_bounds__(256) void k6(float* __restrict__ out) {
    int i = blockIdx.x * 256 + threadIdx.x;
    float v = g_onoff[i & 63] * g_outsm[i];
    out[i] = fmaxf(v, TINY);
    float sc = v * g_scalar[i];
    out[16384 + i] = (fabsf(sc) <= TINY) ? TINY : sc;
}

extern "C" void kernel_launch(void* const* d_in, const int* in_sizes, int n_in,
                              void* d_out, int out_size) {
    const float* x    = (const float*)d_in[0];
    const float* last = (const float*)d_in[1];
    const float* qw   = (const float*)d_in[2];
    const float* w1   = (const float*)d_in[3];
    const float* g1   = (const float*)d_in[4];
    const float* b1   = (const float*)d_in[5];
    const float* w2   = (const float*)d_in[6];
    const float* g2   = (const float*)d_in[7];
    const float* b2   = (const float*)d_in[8];
    const float* ws   = (const float*)d_in[9];
    const float* woo  = (const float*)d_in[10];
    float* out = (float*)d_out;

    k0<<<64, 256>>>(x, qw);
    k1<<<256, 256>>>(w1);
    k2<<<64, 256>>>(g1, b1);
    k3<<<1152, 256>>>(w2, ws);
    k4<<<64, 256>>>(g2, b2, woo);
    k5<<<1, 256>>>(last, woo);
    k6<<<64, 256>>>(out);
}

// round 4
// speedup vs baseline: 2.0064x; 1.1931x over previous
#include <cuda_runtime.h>
#include <math.h>

#define N_INP 128
#define N_HID 512
#define N_OUT 256
#define N_HEADS 64
#define N_SM 4
#define EPS_GN 1e-5f
#define TINY 1e-14f

// Scratch: device globals (no allocation allowed).
__device__ float g_z1[N_HEADS * N_HID];         // pre-GN l1 activations
__device__ float g_z[N_SM * N_HEADS * N_OUT];   // pre-GN l2 activations [s][h][o]
__device__ float g_scalar[N_OUT * N_HEADS];     // ws.sum(-1).T, [o][h]

__device__ __forceinline__ float wsum(float v) {
#pragma unroll
    for (int o = 16; o > 0; o >>= 1) v += __shfl_xor_sync(0xffffffffu, v, o);
    return v;
}
__device__ __forceinline__ float wmax(float v) {
#pragma unroll
    for (int o = 16; o > 0; o >>= 1) v = fmaxf(v, __shfl_xor_sync(0xffffffffu, v, o));
    return v;
}

// ---------------- kA: fused sub = x@qw_h (redundant per block) + w1 chunk matvec ----------------
__global__ __launch_bounds__(256) void kA(const float* __restrict__ x,
                                          const float* __restrict__ qw,
                                          const float* __restrict__ w1) {
    int h = blockIdx.x >> 2, c = blockIdx.x & 3;
    int t = threadIdx.x, w = t >> 5, l = t & 31;
    __shared__ float qs[128], sub[128];
    if (t < 128) qs[t] = qw[h * 128 + t];
    __syncthreads();
    float q0 = qs[l * 4], q1 = qs[l * 4 + 1], q2 = qs[l * 4 + 2], q3 = qs[l * 4 + 3];

    // sub[r] = dot(x[r,:], qw[h,:]) — 8 warps × 16 rows, 8-row ILP (x is L2-resident)
#pragma unroll
    for (int g = 0; g < 2; ++g) {
        int r = w * 16 + g * 8;
        float4 a[8];
        float acc[8];
#pragma unroll
        for (int j = 0; j < 8; ++j)
            a[j] = *(const float4*)(x + (r + j) * 128 + l * 4);
#pragma unroll
        for (int j = 0; j < 8; ++j)
            acc[j] = a[j].x * q0 + a[j].y * q1 + a[j].z * q2 + a[j].w * q3;
#pragma unroll
        for (int j = 0; j < 8; ++j) acc[j] = wsum(acc[j]);
        if (l == 0) {
#pragma unroll
            for (int j = 0; j < 8; ++j) sub[r + j] = acc[j];
        }
    }
    __syncthreads();

    float s0 = sub[l * 4], s1 = sub[l * 4 + 1], s2 = sub[l * 4 + 2], s3 = sub[l * 4 + 3];
    const float* w1b = w1 + (size_t)h * 512 * 128 + (size_t)c * 128 * 128;
    // 128 rows per block, 8 warps -> 16 rows/warp, 8-row ILP
#pragma unroll
    for (int g = 0; g < 2; ++g) {
        int r = w * 16 + g * 8;
        float4 a[8];
        float acc[8];
#pragma unroll
        for (int j = 0; j < 8; ++j)
            a[j] = *(const float4*)(w1b + (r + j) * 128 + l * 4);
#pragma unroll
        for (int j = 0; j < 8; ++j)
            acc[j] = a[j].x * s0 + a[j].y * s1 + a[j].z * s2 + a[j].w * s3;
#pragma unroll
        for (int j = 0; j < 8; ++j) acc[j] = wsum(acc[j]);
        if (l == 0) {
#pragma unroll
            for (int j = 0; j < 8; ++j) g_z1[h * 512 + c * 128 + r + j] = acc[j];
        }
    }
}

// ---------------- kB: fused GN1+softplus (redundant) + w2 stream + ws sums ----------------
__global__ __launch_bounds__(256) void kB(const float* __restrict__ w2,
                                          const float* __restrict__ ws,
                                          const float* __restrict__ g1,
                                          const float* __restrict__ b1) {
    int b = blockIdx.x;
    int t = threadIdx.x, w = t >> 5, l = t & 31;
    if (b < 1024) {
        int c = b & 3, h = (b >> 2) & 63, s = b >> 8;
        __shared__ float h1s[512];
        __shared__ float rs[8], rss[8], stat[2];

        // GN1 + softplus on z1[h] (L2-resident; recomputed per block)
        float v0 = g_z1[h * 512 + t], v1 = g_z1[h * 512 + 256 + t];
        float sv = v0 + v1, sq = v0 * v0 + v1 * v1;
        sv = wsum(sv); sq = wsum(sq);
        if (l == 0) { rs[w] = sv; rss[w] = sq; }
        __syncthreads();
        if (t == 0) {
            float S = 0.f, SS = 0.f;
#pragma unroll
            for (int i = 0; i < 8; ++i) { S += rs[i]; SS += rss[i]; }
            float mu = S / 512.f;
            float var = SS / 512.f - mu * mu;
            stat[0] = mu;
            stat[1] = rsqrtf(fmaxf(var, 0.f) + EPS_GN);
        }
        __syncthreads();
        float mu = stat[0], ri = stat[1];
        float a0 = (v0 - mu) * ri * g1[h * 512 + t] + b1[h * 512 + t];
        float a1 = (v1 - mu) * ri * g1[h * 512 + 256 + t] + b1[h * 512 + 256 + t];
        h1s[t] = fmaxf(a0, 0.f) + log1pf(expf(-fabsf(a0)));
        h1s[t + 256] = fmaxf(a1, 0.f) + log1pf(expf(-fabsf(a1)));
        __syncthreads();

        const float* base = w2 + ((size_t)(s * 64 + h)) * 256 * 512 + (size_t)c * 64 * 512;
        // 64 rows, 8 warps -> 8 rows/warp; 2-row x 4-kchunk ILP
#pragma unroll
        for (int g = 0; g < 4; ++g) {
            int r = w * 8 + g * 2;
            const float* r0 = base + (size_t)r * 512;
            const float* r1 = r0 + 512;
            float4 a[4], bq[4];
#pragma unroll
            for (int k = 0; k < 4; ++k) {
                a[k]  = *(const float4*)(r0 + k * 128 + l * 4);
                bq[k] = *(const float4*)(r1 + k * 128 + l * 4);
            }
            float d0 = 0.f, d1 = 0.f;
#pragma unroll
            for (int k = 0; k < 4; ++k) {
                int i = k * 128 + l * 4;
                d0 += a[k].x * h1s[i] + a[k].y * h1s[i + 1] + a[k].z * h1s[i + 2] + a[k].w * h1s[i + 3];
                d1 += bq[k].x * h1s[i] + bq[k].y * h1s[i + 1] + bq[k].z * h1s[i + 2] + bq[k].w * h1s[i + 3];
            }
            d0 = wsum(d0); d1 = wsum(d1);
            if (l == 0) {
                size_t o = (size_t)(s * 64 + h) * 256 + c * 64 + r;
                g_z[o] = d0;
                g_z[o + 1] = d1;
            }
        }
    } else {
        // ws row-sums: scalar[o][h] = sum_j ws[h][o][j]
        int idx = b - 1024;
        int h = idx >> 1, half = idx & 1;
        const float* base = ws + (size_t)h * 256 * 256 + (size_t)half * 128 * 256;
#pragma unroll
        for (int g = 0; g < 4; ++g) {
            int r = w * 16 + g * 4;
            float acc[4] = {0.f, 0.f, 0.f, 0.f};
            float4 a[8];
#pragma unroll
            for (int j = 0; j < 4; ++j) {
#pragma unroll
                for (int k = 0; k < 2; ++k)
                    a[j * 2 + k] = *(const float4*)(base + (size_t)(r + j) * 256 + k * 128 + l * 4);
            }
#pragma unroll
            for (int j = 0; j < 4; ++j) {
#pragma unroll
                for (int k = 0; k < 2; ++k)
                    acc[j] += a[j * 2 + k].x + a[j * 2 + k].y + a[j * 2 + k].z + a[j * 2 + k].w;
            }
#pragma unroll
            for (int j = 0; j < 4; ++j) acc[j] = wsum(acc[j]);
            if (l == 0) {
                int o = half * 128 + r;
#pragma unroll
                for (int j = 0; j < 4; ++j) g_scalar[(o + j) * 64 + h] = acc[j];
            }
        }
    }
}

// ---------------- kC: per-head GN2+softmax+sum_s + full gate + final outputs ----------------
__global__ __launch_bounds__(256) void kC(const float* __restrict__ g2,
                                          const float* __restrict__ b2,
                                          const float* __restrict__ woo,
                                          const float* __restrict__ last,
                                          float* __restrict__ out) {
    int h = blockIdx.x, t = threadIdx.x, w = t >> 5, l = t & 31;
    __shared__ float r1[8], r2[8], stat[2];
    __shared__ float onoff_s;

    // last_prod[t] = prod over heads of last[t, :]  (redundant per block, L2-resident)
    float lp;
    {
        const float* lo = last + t * 64;
        float p = 1.f;
#pragma unroll 8
        for (int i = 0; i < 64; ++i) p *= lo[i];
        lp = p;
    }

    float acc = 0.f;
#pragma unroll
    for (int s = 0; s < 4; ++s) {
        size_t gi = (size_t)(s * 64 + h) * 256;
        float v = g_z[gi + t];
        float sv = wsum(v), sq = wsum(v * v);
        if (l == 0) { r1[w] = sv; r2[w] = sq; }
        __syncthreads();
        if (t == 0) {
            float S = 0.f, SS = 0.f;
#pragma unroll
            for (int i = 0; i < 8; ++i) { S += r1[i]; SS += r2[i]; }
            float mu = S / 256.f;
            float var = SS / 256.f - mu * mu;
            stat[0] = mu;
            stat[1] = rsqrtf(fmaxf(var, 0.f) + EPS_GN);
        }
        __syncthreads();
        float z = (v - stat[0]) * stat[1] * g2[gi + t] + b2[gi + t];
        __syncthreads();
        float m = wmax(z);
        if (l == 0) r1[w] = m;
        __syncthreads();
        if (t == 0) {
            float M = -1e30f;
#pragma unroll
            for (int i = 0; i < 8; ++i) M = fmaxf(M, r1[i]);
            stat[0] = M;
        }
        __syncthreads();
        float e = expf(z - stat[0]);
        float se = wsum(e);
        if (l == 0) r2[w] = se;
        __syncthreads();
        if (t == 0) {
            float S = 0.f;
#pragma unroll
            for (int i = 0; i < 8; ++i) S += r2[i];
            stat[1] = S;
        }
        __syncthreads();
        acc += e / stat[1];
        __syncthreads();
    }

    // gate: woo[h,:256] @ lp + woo[h,256:] @ outsm[:,h]
    float gp = woo[h * 512 + t] * lp + woo[h * 512 + 256 + t] * acc;
    gp = wsum(gp);
    if (l == 0) r1[w] = gp;
    __syncthreads();
    if (t == 0) {
        float S = 0.f;
#pragma unroll
        for (int i = 0; i < 8; ++i) S += r1[i];
        onoff_s = 1.f / (1.f + expf(-S));
    }
    __syncthreads();

    float v = onoff_s * acc;
    out[t * 64 + h] = fmaxf(v, TINY);
    float sc = v * g_scalar[t * 64 + h];
    out[16384 + t * 64 + h] = (fabsf(sc) <= TINY) ? TINY : sc;
}

extern "C" void kernel_launch(void* const* d_in, const int* in_sizes, int n_in,
                              void* d_out, int out_size) {
    const float* x    = (const float*)d_in[0];
    const float* last = (const float*)d_in[1];
    const float* qw   = (const float*)d_in[2];
    const float* w1   = (const float*)d_in[3];
    const float* g1   = (const float*)d_in[4];
    const float* b1   = (const float*)d_in[5];
    const float* w2   = (const float*)d_in[6];
    const float* g2   = (const float*)d_in[7];
    const float* b2   = (const float*)d_in[8];
    const float* ws   = (const float*)d_in[9];
    const float* woo  = (const float*)d_in[10];
    float* out = (float*)d_out;

    kA<<<256, 256>>>(x, qw, w1);
    kB<<<1152, 256>>>(w2, ws, g1, b1);
    kC<<<64, 256>>>(g2, b2, woo, last, out);
}